// round 3
// baseline (speedup 1.0000x reference)
#include <cuda_runtime.h>

// QueryEncDec: 2x128-layer scalar GRU (H=in=1), T=256, fused as one 256-layer
// wavefront across 8 warps. Intra-warp handoff = shuffle (no sync). Warp
// boundaries = write-once smem buffer + per-8-step monotonic release/acquire
// counter; waiting warps park with __nanosleep (no spin burn).
//
// out[0:256]   = dec_out  (layer 255 output at each t)
// out[256:384] = dec_h    (final hidden of global layers 128..255)

#define GRU_T   256
#define NW      8
#define KC      8              // chunk: steps between boundary syncs
#define NCHUNK  36             // 36*8 = 288 >= 287 inner steps

__device__ __forceinline__ float frcp(float a) {
    float r; asm("rcp.approx.f32 %0, %1;" : "=f"(r) : "f"(a)); return r;
}
__device__ __forceinline__ float fex2(float a) {
    float r; asm("ex2.approx.f32 %0, %1;" : "=f"(r) : "f"(a)); return r;
}

__global__ __launch_bounds__(256, 1)
void gru_wave_chunk(const float* __restrict__ X,
                    const float* __restrict__ ewi, const float* __restrict__ ewh,
                    const float* __restrict__ ebi, const float* __restrict__ ebh,
                    const float* __restrict__ dwi, const float* __restrict__ dwh,
                    const float* __restrict__ dbi, const float* __restrict__ dbh,
                    float* __restrict__ out)
{
    const int tid  = threadIdx.x;
    const int l    = tid;           // global layer 0..255
    const int w    = tid >> 5;
    const int lane = tid & 31;

    __shared__ __align__(16) float xs[GRU_T];
    __shared__ __align__(16) float bb[NW - 1][GRU_T];  // boundary outputs
    __shared__ int flags[NW - 1];                      // chunks published

    if (tid < NW - 1) flags[tid] = 0;
    if (tid < GRU_T)  xs[tid] = X[tid];

    // per-layer scalar weights (torch gate order r,z,n)
    const bool  enc = (l < 128);
    const int   li  = enc ? l : (l - 128);
    const float* wi = enc ? ewi : dwi;
    const float* wh = enc ? ewh : dwh;
    const float* bi = enc ? ebi : dbi;
    const float* bh = enc ? ebh : dbh;

    const float wi_r = wi[li*3+0], wi_z = wi[li*3+1], wi_n = wi[li*3+2];
    const float wh_r = wh[li*3+0], wh_z = wh[li*3+1], wh_n = wh[li*3+2];
    const float bi_r = bi[li*3+0], bi_z = bi[li*3+1], bi_n = bi[li*3+2];
    const float bh_r = bh[li*3+0], bh_z = bh[li*3+1], bh_n = bh[li*3+2];

    const float L2E = 1.4426950408889634f;
    const float Kt  = -2.0f * L2E;

    // sigmoid(u) = rcp(1 + ex2(-u*log2e)); tanh(a) = 2*rcp(1+ex2(-2a*log2e)) - 1
    const float nwi_r = -wi_r * L2E,  nwi_z = -wi_z * L2E;
    const float Lwh_r = -wh_r * L2E,  Lwh_z = -wh_z * L2E;
    const float Lsb_r = -(bi_r + bh_r) * L2E;
    const float Lsb_z = -(bi_z + bh_z) * L2E;
    const float kwi_n = Kt * wi_n, kbi_n = Kt * bi_n;
    const float kwh_n = Kt * wh_n, kbh_n = Kt * bh_n;

    float h   = 0.0f;
    float hp1 = 1.0f;            // h + 1
    float nc_r = Lsb_r;          // fma(Lwh_r, h, Lsb_r) with h=0
    float nc_z = Lsb_z;
    float gh2  = kbh_n;          // fma(kwh_n, h, kbh_n)

    __syncthreads();             // xs + flags visible

    const float* inbox  = (w == 0) ? xs : bb[w - 1];
    float*       outbox = (w < NW - 1) ? bb[w] : bb[0];  // unused for w==7
    const bool   is_prod = (lane == 31) && (w < NW - 1);

    unsigned flag_rd = 0, flag_wr = 0;
    if (w > 0)
        flag_rd = (unsigned)__cvta_generic_to_shared(&flags[w - 1]);
    if (w < NW - 1)
        flag_wr = (unsigned)__cvta_generic_to_shared(&flags[w]);

    #pragma unroll 1
    for (int ic = 0; ic < NCHUNK; ++ic) {
        // lane 0: acquire this chunk's 8 inbox values (t = ic*8 .. ic*8+7)
        float p0x=0,p0y=0,p0z=0,p0w=0, p1x=0,p1y=0,p1z=0,p1w=0;
        if (lane == 0 && ic < GRU_T / KC) {
            if (w > 0) {
                const int need = ic + 1;
                int v;
                while (true) {
                    asm volatile("ld.acquire.cta.shared.b32 %0, [%1];"
                                 : "=r"(v) : "r"(flag_rd) : "memory");
                    if (v >= need) break;
                    __nanosleep(64);
                }
            }
            float4 a = *(const float4*)(inbox + ic * KC);
            float4 b = *(const float4*)(inbox + ic * KC + 4);
            p0x=a.x; p0y=a.y; p0z=a.z; p0w=a.w;
            p1x=b.x; p1y=b.y; p1z=b.z; p1w=b.w;
        }

        #pragma unroll
        for (int u = 0; u < KC; ++u) {
            const int j = ic * KC + u;
            const int t = j - lane;

            float x = __shfl_up_sync(0xFFFFFFFFu, h, 1);
            if (lane == 0) {
                float pv;
                switch (u) {
                    case 0: pv = p0x; break;  case 1: pv = p0y; break;
                    case 2: pv = p0z; break;  case 3: pv = p0w; break;
                    case 4: pv = p1x; break;  case 5: pv = p1y; break;
                    case 6: pv = p1z; break;  default: pv = p1w; break;
                }
                x = pv;
            }

            if (t >= 0 && t < GRU_T) {
                // r, z gates (independent MUFU chains)
                const float er = fex2(fmaf(nwi_r, x, nc_r));
                const float r  = frcp(1.0f + er);
                const float ez = fex2(fmaf(nwi_z, x, nc_z));
                const float z  = frcp(1.0f + ez);
                // n = tanh(wi_n*x + bi_n + r*(wh_n*h + bh_n)) = 2s - 1
                const float e2 = fex2(fmaf(r, gh2, fmaf(kwi_n, x, kbi_n)));
                const float s  = frcp(1.0f + e2);
                // h' = (1-z)*n + z*h = s*(2-2z) + (z*(h+1) - 1)
                const float p  = fmaf(z, hp1, -1.0f);
                const float q  = fmaf(-2.0f, z, 2.0f);
                h = fmaf(s, q, p);

                if (is_prod) outbox[t] = h;      // plain STS, off-chain

                hp1  = h + 1.0f;
                nc_r = fmaf(Lwh_r, h, Lsb_r);
                nc_z = fmaf(Lwh_z, h, Lsb_z);
                gh2  = fmaf(kwh_n, h, kbh_n);

                if (l == 255)                 out[t] = h;                   // dec_out
                if (t == GRU_T - 1 && l >= 128) out[GRU_T + (l - 128)] = h; // dec_h
            }
        }

        // publish: after inner chunk ic, t-chunks 0..ic-4 are complete
        if (is_prod && ic >= 4) {
            const int val = ic - 3;
            asm volatile("st.release.cta.shared.b32 [%0], %1;"
                         :: "r"(flag_wr), "r"(val) : "memory");
        }
    }
}

extern "C" void kernel_launch(void* const* d_in, const int* in_sizes, int n_in,
                              void* d_out, int out_size)
{
    const float* X   = (const float*)d_in[0];
    const float* ewi = (const float*)d_in[1];
    const float* ewh = (const float*)d_in[2];
    const float* ebi = (const float*)d_in[3];
    const float* ebh = (const float*)d_in[4];
    const float* dwi = (const float*)d_in[5];
    const float* dwh = (const float*)d_in[6];
    const float* dbi = (const float*)d_in[7];
    const float* dbh = (const float*)d_in[8];
    float* out = (float*)d_out;

    gru_wave_chunk<<<1, 256>>>(X, ewi, ewh, ebi, ebh, dwi, dwh, dbi, dbh, out);
}

// round 4
// speedup vs baseline: 2.9563x; 2.9563x over previous
#include <cuda_runtime.h>

// QueryEncDec: 2x128-layer scalar GRU (H=in=1), T=256, fused 256-layer wavefront.
// Intra-warp layer handoff: __shfl_up (no sync). Warp boundaries: write-once
// smem buffers + named-barrier producer/consumer sync once per 8 steps
// (bar.arrive = non-blocking producer, bar.sync = HW-parked consumer).
//
// out[0:256]   = dec_out  (layer 255 output at each t)
// out[256:384] = dec_h    (final hidden of global layers 128..255)

#define GRU_T 256
#define NW    8
#define KC    8      // steps per chunk
#define NCH   36     // 36*8 = 288 >= 287 inner steps

__device__ __forceinline__ float frcp(float a) {
    float r; asm("rcp.approx.f32 %0, %1;" : "=f"(r) : "f"(a)); return r;
}
__device__ __forceinline__ float fex2(float a) {
    float r; asm("ex2.approx.f32 %0, %1;" : "=f"(r) : "f"(a)); return r;
}

__global__ __launch_bounds__(256, 1)
void gru_wave_nbar(const float* __restrict__ X,
                   const float* __restrict__ ewi, const float* __restrict__ ewh,
                   const float* __restrict__ ebi, const float* __restrict__ ebh,
                   const float* __restrict__ dwi, const float* __restrict__ dwh,
                   const float* __restrict__ dbi, const float* __restrict__ dbh,
                   float* __restrict__ out)
{
    const int tid  = threadIdx.x;
    const int l    = tid;          // global layer 0..255
    const int w    = tid >> 5;
    const int lane = tid & 31;

    __shared__ __align__(16) float xs[GRU_T];
    __shared__ __align__(16) float bb[NW - 1][GRU_T];  // boundary outputs (write-once)
    __shared__ int rel_scratch[NW];                     // release-store targets

    if (tid < GRU_T) xs[tid] = X[tid];

    // per-layer scalar weights (torch gate order r,z,n)
    const bool  enc = (l < 128);
    const int   li  = enc ? l : (l - 128);
    const float* wi = enc ? ewi : dwi;
    const float* wh = enc ? ewh : dwh;
    const float* bi = enc ? ebi : dbi;
    const float* bh = enc ? ebh : dbh;

    const float wi_r = wi[li*3+0], wi_z = wi[li*3+1], wi_n = wi[li*3+2];
    const float wh_r = wh[li*3+0], wh_z = wh[li*3+1], wh_n = wh[li*3+2];
    const float bi_r = bi[li*3+0], bi_z = bi[li*3+1], bi_n = bi[li*3+2];
    const float bh_r = bh[li*3+0], bh_z = bh[li*3+1], bh_n = bh[li*3+2];

    const float L2E = 1.4426950408889634f;
    const float Kt  = -2.0f * L2E;

    // sigmoid(u) = rcp(1 + ex2(-u*log2e)); tanh(a) = 2*rcp(1 + ex2(-2a*log2e)) - 1
    const float nwi_r = -wi_r * L2E,  nwi_z = -wi_z * L2E;
    const float Lwh_r = -wh_r * L2E,  Lwh_z = -wh_z * L2E;
    const float Lsb_r = -(bi_r + bh_r) * L2E;
    const float Lsb_z = -(bi_z + bh_z) * L2E;
    const float kwi_n = Kt * wi_n, kbi_n = Kt * bi_n;
    const float kwh_n = Kt * wh_n, kbh_n = Kt * bh_n;

    float h    = 0.0f;
    float hp1  = 1.0f;            // h + 1
    float nc_r = Lsb_r;           // fma(Lwh_r, h, Lsb_r) at h=0
    float nc_z = Lsb_z;
    float gh2  = kbh_n;

    __syncthreads();              // xs visible

    const float* inbox  = (w == 0) ? xs : bb[w - 1];
    float*       outbox = (w < NW - 1) ? bb[w] : bb[0];   // unused for w==7
    const bool   is_prod = (lane == 31) && (w < NW - 1);
    const unsigned rel_addr =
        (unsigned)__cvta_generic_to_shared(&rel_scratch[w]);

    #pragma unroll 1
    for (int ic = 0; ic < NCH; ++ic) {
        // ---- consumer: wait for upstream chunk ic, then prefetch 8 values ----
        if (w > 0 && ic < GRU_T / KC) {
            asm volatile("bar.sync %0, %1;" :: "r"(w), "r"(64) : "memory");
        }
        float pf[KC];
        if (lane == 0 && ic < GRU_T / KC) {
            float4 a = *(const float4*)(inbox + ic * KC);
            float4 b = *(const float4*)(inbox + ic * KC + 4);
            pf[0]=a.x; pf[1]=a.y; pf[2]=a.z; pf[3]=a.w;
            pf[4]=b.x; pf[5]=b.y; pf[6]=b.z; pf[7]=b.w;
        }

        // ---- 8 wavefront steps ----
        #pragma unroll
        for (int u = 0; u < KC; ++u) {
            const int j = ic * KC + u;
            const int t = j - lane;
            const bool valid = (t >= 0) && (t < GRU_T);

            float x = __shfl_up_sync(0xFFFFFFFFu, h, 1);
            if (lane == 0) x = pf[u];

            // r, z gates (independent MUFU chains)
            const float er = fex2(fmaf(nwi_r, x, nc_r));
            const float r  = frcp(1.0f + er);
            const float ez = fex2(fmaf(nwi_z, x, nc_z));
            const float z  = frcp(1.0f + ez);
            // n = tanh(...) = 2s - 1;  h' = s*(2-2z) + (z*(h+1) - 1)
            const float e2 = fex2(fmaf(r, gh2, fmaf(kwi_n, x, kbi_n)));
            const float s  = frcp(1.0f + e2);
            const float p  = fmaf(z, hp1, -1.0f);
            const float q  = fmaf(-2.0f, z, 2.0f);
            const float hn = fmaf(s, q, p);

            if (valid) h = hn;                 // predicated write

            if (is_prod && valid) outbox[t] = h;   // plain STS, off-chain

            hp1  = h + 1.0f;
            nc_r = fmaf(Lwh_r, h, Lsb_r);
            nc_z = fmaf(Lwh_z, h, Lsb_z);
            gh2  = fmaf(kwh_n, h, kbh_n);

            if (l == 255 && valid)            out[t] = h;                   // dec_out
            if (t == GRU_T - 1 && l >= 128)   out[GRU_T + (l - 128)] = h;   // dec_h
        }

        // ---- producer: publish t-chunk (ic-4); it completed at step 8*ic+6 ----
        if (w < NW - 1 && ic >= 4) {
            if (is_prod) {   // order the chunk's STS before the arrive
                asm volatile("st.release.cta.shared.b32 [%0], %1;"
                             :: "r"(rel_addr), "r"(ic) : "memory");
            }
            asm volatile("bar.arrive %0, %1;" :: "r"(w + 1), "r"(64) : "memory");
        }
    }
}

extern "C" void kernel_launch(void* const* d_in, const int* in_sizes, int n_in,
                              void* d_out, int out_size)
{
    const float* X   = (const float*)d_in[0];
    const float* ewi = (const float*)d_in[1];
    const float* ewh = (const float*)d_in[2];
    const float* ebi = (const float*)d_in[3];
    const float* ebh = (const float*)d_in[4];
    const float* dwi = (const float*)d_in[5];
    const float* dwh = (const float*)d_in[6];
    const float* dbi = (const float*)d_in[7];
    const float* dbh = (const float*)d_in[8];
    float* out = (float*)d_out;

    gru_wave_nbar<<<1, 256>>>(X, ewi, ewh, ebi, ebh, dwi, dwh, dbi, dbh, out);
}

// round 5
// speedup vs baseline: 3.8702x; 1.3091x over previous
#include <cuda_runtime.h>

// QueryEncDec: 2x128-layer scalar GRU (H=in=1), T=256, fused 256-layer wavefront.
// Intra-warp layer handoff: __shfl_up. Warp boundaries: write-once smem buffers
// + named-barrier producer/consumer sync per 8-step chunk.
// r/z gates via tanh.approx (1 MUFU each); n-gate exact via ex2+rcp.
//
// out[0:256]   = dec_out  (layer 255 output at each t)
// out[256:384] = dec_h    (final hidden of global layers 128..255)

#define GRU_T 256
#define NW    8
#define KC    8
#define NCH   36     // 36*8 = 288 >= 287 inner steps

__device__ __forceinline__ float frcp(float a) {
    float r; asm("rcp.approx.f32 %0, %1;" : "=f"(r) : "f"(a)); return r;
}
__device__ __forceinline__ float fex2(float a) {
    float r; asm("ex2.approx.f32 %0, %1;" : "=f"(r) : "f"(a)); return r;
}
__device__ __forceinline__ float ftanh(float a) {
    float r; asm("tanh.approx.f32 %0, %1;" : "=f"(r) : "f"(a)); return r;
}

__global__ __launch_bounds__(256, 1)
void gru_wave_v5(const float* __restrict__ X,
                 const float* __restrict__ ewi, const float* __restrict__ ewh,
                 const float* __restrict__ ebi, const float* __restrict__ ebh,
                 const float* __restrict__ dwi, const float* __restrict__ dwh,
                 const float* __restrict__ dbi, const float* __restrict__ dbh,
                 float* __restrict__ out)
{
    const int tid  = threadIdx.x;
    const int l    = tid;          // global layer 0..255
    const int w    = tid >> 5;
    const int lane = tid & 31;

    __shared__ __align__(16) float xs[GRU_T];
    __shared__ __align__(16) float bb[NW - 1][GRU_T];   // boundary outputs
    __shared__ int rel_scratch[NW];

    if (tid < GRU_T) xs[tid] = X[tid];

    // per-layer scalar weights (torch gate order r,z,n)
    const bool  enc = (l < 128);
    const int   li  = enc ? l : (l - 128);
    const float* wi = enc ? ewi : dwi;
    const float* wh = enc ? ewh : dwh;
    const float* bi = enc ? ebi : dbi;
    const float* bh = enc ? ebh : dbh;

    const float wi_r = wi[li*3+0], wi_z = wi[li*3+1], wi_n = wi[li*3+2];
    const float wh_r = wh[li*3+0], wh_z = wh[li*3+1], wh_n = wh[li*3+2];
    const float bi_r = bi[li*3+0], bi_z = bi[li*3+1], bi_n = bi[li*3+2];
    const float bh_r = bh[li*3+0], bh_z = bh[li*3+1], bh_n = bh[li*3+2];

    const float L2E = 1.4426950408889634f;
    const float Kt  = -2.0f * L2E;              // for n-gate ex2

    // r: sigmoid(u) = 0.5 + 0.5*tanh(u/2) -> half-scaled weights
    const float hwi_r = 0.5f * wi_r, hwh_r = 0.5f * wh_r;
    const float hb_r  = 0.5f * (bi_r + bh_r);
    // z likewise
    const float hwi_z = 0.5f * wi_z, hwh_z = 0.5f * wh_z;
    const float hb_z  = 0.5f * (bi_z + bh_z);
    // n: e2 = ex2(K*(wi_n x + bi_n) + r * K*(wh_n h + bh_n))
    const float kwi_n = Kt * wi_n, kbi_n = Kt * bi_n;
    // gh_k_half = 0.5*K*(wh_n h + bh_n): r*ghk = fma(gh_k_half, t_r, gh_k_half)
    const float khwh_n = 0.5f * Kt * wh_n, khbh_n = 0.5f * Kt * bh_n;

    float h        = 0.0f;
    float nc_r     = hb_r;         // fma(hwh_r, h, hb_r) at h=0
    float nc_z     = hb_z;
    float ghk_half = khbh_n;       // fma(khwh_n, h, khbh_n)
    float hp1      = 1.0f;         // h + 1
    float hm_half  = -0.5f;        // 0.5h - 0.5

    __syncthreads();

    const float* inbox  = (w == 0) ? xs : bb[w - 1];
    float*       outbox = (w < NW - 1) ? bb[w] : bb[0];
    const bool   is_prod = (lane == 31) && (w < NW - 1);
    const unsigned rel_addr =
        (unsigned)__cvta_generic_to_shared(&rel_scratch[w]);

    #pragma unroll 1
    for (int ic = 0; ic < NCH; ++ic) {
        // consumer: wait for upstream chunk ic, prefetch 8 inbox values
        if (w > 0 && ic < GRU_T / KC) {
            asm volatile("bar.sync %0, %1;" :: "r"(w), "r"(64) : "memory");
        }
        float pf[KC];
        if (lane == 0 && ic < GRU_T / KC) {
            float4 a = *(const float4*)(inbox + ic * KC);
            float4 b = *(const float4*)(inbox + ic * KC + 4);
            pf[0]=a.x; pf[1]=a.y; pf[2]=a.z; pf[3]=a.w;
            pf[4]=b.x; pf[5]=b.y; pf[6]=b.z; pf[7]=b.w;
        }

        #pragma unroll
        for (int u = 0; u < KC; ++u) {
            const int j = ic * KC + u;
            const int t = j - lane;
            const bool valid = (t >= 0) && (t < GRU_T);

            float x = __shfl_up_sync(0xFFFFFFFFu, h, 1);
            if (lane == 0) x = pf[u];

            // r-gate (tanh chain, on x critical path)
            const float t_r = ftanh(fmaf(hwi_r, x, nc_r));
            // z-gate (parallel tanh chain)
            const float t_z = ftanh(fmaf(hwi_z, x, nc_z));
            // n-gate: u2 = K*(wi_n x + bi_n) + r*K*gh_n
            const float xin   = fmaf(kwi_n, x, kbi_n);       // parallel
            const float rterm = fmaf(ghk_half, t_r, ghk_half);
            const float e2    = fex2(xin + rterm);
            const float s     = frcp(1.0f + e2);             // s = (n+1)/2
            // h' = (1-z)n + zh = q*s + p,
            //   q = 1 - t_z,  p = fma(0.5 t_z, h+1, 0.5h - 0.5)
            const float q  = 1.0f - t_z;
            const float p  = fmaf(0.5f * t_z, hp1, hm_half);
            const float hn = fmaf(q, s, p);

            if (valid) h = hn;

            if (is_prod && valid) outbox[t] = h;   // plain STS, off-chain

            // tail: next step's h-dependent terms (parallel, off x-chain)
            nc_r     = fmaf(hwh_r, h, hb_r);
            nc_z     = fmaf(hwh_z, h, hb_z);
            ghk_half = fmaf(khwh_n, h, khbh_n);
            hp1      = h + 1.0f;
            hm_half  = fmaf(0.5f, h, -0.5f);

            if (l == 255 && valid)          out[t] = h;                   // dec_out
            if (t == GRU_T - 1 && l >= 128) out[GRU_T + (l - 128)] = h;   // dec_h
        }

        // producer: publish t-chunk ic-4 (complete at inner step 8*ic+6)
        if (w < NW - 1 && ic >= 4) {
            if (is_prod) {
                asm volatile("st.release.cta.shared.b32 [%0], %1;"
                             :: "r"(rel_addr), "r"(ic) : "memory");
            }
            asm volatile("bar.arrive %0, %1;" :: "r"(w + 1), "r"(64) : "memory");
        }
    }
}

extern "C" void kernel_launch(void* const* d_in, const int* in_sizes, int n_in,
                              void* d_out, int out_size)
{
    const float* X   = (const float*)d_in[0];
    const float* ewi = (const float*)d_in[1];
    const float* ewh = (const float*)d_in[2];
    const float* ebi = (const float*)d_in[3];
    const float* ebh = (const float*)d_in[4];
    const float* dwi = (const float*)d_in[5];
    const float* dwh = (const float*)d_in[6];
    const float* dbi = (const float*)d_in[7];
    const float* dbh = (const float*)d_in[8];
    float* out = (float*)d_out;

    gru_wave_v5<<<1, 256>>>(X, ewi, ewh, ebi, ebh, dwi, dwh, dbi, dbh, out);
}

// round 6
// speedup vs baseline: 5.5255x; 1.4277x over previous
#include <cuda_runtime.h>

// QueryEncDec: 2x128-layer scalar GRU (H=in=1), T=256, fused 256-layer wavefront.
// Intra-warp layer handoff: __shfl_up. Warp boundaries: write-once smem buffers
// + named-barrier producer/consumer sync per 8-step chunk.
// ALL THREE gates via tanh.approx (3 MUFU/step); x-chain ~ shfl+fma+tanh+fma+tanh+fma.
//
// out[0:256]   = dec_out  (layer 255 output at each t)
// out[256:384] = dec_h    (final hidden of global layers 128..255)

#define GRU_T 256
#define NW    8
#define KC    8
#define NCH   36     // 36*8 = 288 >= 287 inner steps

__device__ __forceinline__ float ftanh(float a) {
    float r; asm("tanh.approx.f32 %0, %1;" : "=f"(r) : "f"(a)); return r;
}

__global__ __launch_bounds__(256, 1)
void gru_wave_v6(const float* __restrict__ X,
                 const float* __restrict__ ewi, const float* __restrict__ ewh,
                 const float* __restrict__ ebi, const float* __restrict__ ebh,
                 const float* __restrict__ dwi, const float* __restrict__ dwh,
                 const float* __restrict__ dbi, const float* __restrict__ dbh,
                 float* __restrict__ out)
{
    const int tid  = threadIdx.x;
    const int l    = tid;          // global layer 0..255
    const int w    = tid >> 5;
    const int lane = tid & 31;

    __shared__ __align__(16) float xs[GRU_T];
    __shared__ __align__(16) float bb[NW - 1][GRU_T];   // boundary outputs
    __shared__ int rel_scratch[NW];

    if (tid < GRU_T) xs[tid] = X[tid];

    // per-layer scalar weights (torch gate order r,z,n)
    const bool  enc = (l < 128);
    const int   li  = enc ? l : (l - 128);
    const float* wi = enc ? ewi : dwi;
    const float* wh = enc ? ewh : dwh;
    const float* bi = enc ? ebi : dbi;
    const float* bh = enc ? ebh : dbh;

    const float wi_r = wi[li*3+0], wi_z = wi[li*3+1], wi_n = wi[li*3+2];
    const float wh_r = wh[li*3+0], wh_z = wh[li*3+1], wh_n = wh[li*3+2];
    const float bi_r = bi[li*3+0], bi_z = bi[li*3+1], bi_n = bi[li*3+2];
    const float bh_r = bh[li*3+0], bh_z = bh[li*3+1], bh_n = bh[li*3+2];

    // r,z: sigmoid(u) = 0.5 + 0.5*tanh(u/2) -> half-scaled args (no post-scale
    // needed: we only use t_r, t_z = tanh(u/2) directly in folded forms)
    const float hwi_r = 0.5f * wi_r, hwh_r = 0.5f * wh_r;
    const float hb_r  = 0.5f * (bi_r + bh_r);
    const float hwi_z = 0.5f * wi_z, hwh_z = 0.5f * wh_z;
    const float hb_z  = 0.5f * (bi_z + bh_z);
    // n-gate: a_n = wi_n*x + bi_n + r*(wh_n*h + bh_n),  r = 0.5 + 0.5*t_r
    //       = xn + 0.5*ghn + 0.5*t_r*ghn,  xn = fma(wi_n,x,bi_n), ghn = fma(wh_n,h,bh_n)
    //       = fma(0.5*ghn, t_r, xn + 0.5*ghn)

    float h    = 0.0f;
    float nc_r = hb_r;            // fma(hwh_r, h, hb_r) at h=0
    float nc_z = hb_z;
    float ghn_h = 0.5f * bh_n;    // 0.5*(wh_n*h + bh_n) at h=0
    float hhalf = 0.0f;           // 0.5*h

    __syncthreads();

    const float* inbox  = (w == 0) ? xs : bb[w - 1];
    float*       outbox = (w < NW - 1) ? bb[w] : bb[0];
    const bool   is_prod = (lane == 31) && (w < NW - 1);
    const unsigned rel_addr =
        (unsigned)__cvta_generic_to_shared(&rel_scratch[w]);

    #pragma unroll 1
    for (int ic = 0; ic < NCH; ++ic) {
        // consumer: wait for upstream chunk ic, prefetch 8 inbox values
        if (w > 0 && ic < GRU_T / KC) {
            asm volatile("bar.sync %0, %1;" :: "r"(w), "r"(64) : "memory");
        }
        float pf[KC];
        if (lane == 0 && ic < GRU_T / KC) {
            float4 a = *(const float4*)(inbox + ic * KC);
            float4 b = *(const float4*)(inbox + ic * KC + 4);
            pf[0]=a.x; pf[1]=a.y; pf[2]=a.z; pf[3]=a.w;
            pf[4]=b.x; pf[5]=b.y; pf[6]=b.z; pf[7]=b.w;
        }

        #pragma unroll
        for (int u = 0; u < KC; ++u) {
            const int j = ic * KC + u;
            const int t = j - lane;
            const bool valid = (t >= 0) && (t < GRU_T);

            float x = __shfl_up_sync(0xFFFFFFFFu, h, 1);
            if (lane == 0) x = pf[u];

            // r-gate (on x critical path)
            const float t_r = ftanh(fmaf(hwi_r, x, nc_r));
            // z-gate (parallel chain)
            const float t_z = ftanh(fmaf(hwi_z, x, nc_z));
            // n-gate: a_n = fma(ghn_h, t_r, xn + ghn_h)
            const float xn  = fmaf(wi_n, x, bi_n);      // x-parallel
            const float t_n = ftanh(fmaf(ghn_h, t_r, xn + ghn_h));
            // h' = (1-z)*n + z*h, z = 0.5+0.5*t_z, n = t_n
            //    = (0.5 - 0.5*t_z)*t_n + 0.5*h*(1 + t_z)
            const float A  = fmaf(-0.5f, t_z, 0.5f);    // t_z-parallel
            const float C  = fmaf(hhalf, t_z, hhalf);   // t_z-parallel
            const float hn = fmaf(A, t_n, C);

            if (valid) h = hn;

            if (is_prod && valid) outbox[t] = h;        // plain STS, off-chain

            // tail: next step's h-dependent terms (off x-chain)
            nc_r  = fmaf(hwh_r, h, hb_r);
            nc_z  = fmaf(hwh_z, h, hb_z);
            ghn_h = fmaf(0.5f * wh_n, h, 0.5f * bh_n);
            hhalf = 0.5f * h;

            if (l == 255 && valid)          out[t] = h;                   // dec_out
            if (t == GRU_T - 1 && l >= 128) out[GRU_T + (l - 128)] = h;   // dec_h
        }

        // producer: publish t-chunk ic-4 (complete at inner step 8*ic+6)
        if (w < NW - 1 && ic >= 4) {
            if (is_prod) {
                asm volatile("st.release.cta.shared.b32 [%0], %1;"
                             :: "r"(rel_addr), "r"(ic) : "memory");
            }
            asm volatile("bar.arrive %0, %1;" :: "r"(w + 1), "r"(64) : "memory");
        }
    }
}

extern "C" void kernel_launch(void* const* d_in, const int* in_sizes, int n_in,
                              void* d_out, int out_size)
{
    const float* X   = (const float*)d_in[0];
    const float* ewi = (const float*)d_in[1];
    const float* ewh = (const float*)d_in[2];
    const float* ebi = (const float*)d_in[3];
    const float* ebh = (const float*)d_in[4];
    const float* dwi = (const float*)d_in[5];
    const float* dwh = (const float*)d_in[6];
    const float* dbi = (const float*)d_in[7];
    const float* dbh = (const float*)d_in[8];
    float* out = (float*)d_out;

    gru_wave_v6<<<1, 256>>>(X, ewi, ewh, ebi, ebh, dwi, dwh, dbi, dbh, out);
}